// round 12
// baseline (speedup 1.0000x reference)
#include <cuda_runtime.h>
#include <cuda_bf16.h>

// NBVLoss: weighted BCE reduction (HBM-bound streaming sum, ~1.07 GB read).
//   out = 10 * sum_{t==1} -max(log(p), -100) + 1 * sum_{t==0} -max(log(1-p), -100)
// target is exactly 0/1 -> one MUFU.LG2 per element; math fully hidden.
//
// FINAL. Converged configuration after an 11-round sweep:
//  - single __logf per element (R2: 296 -> 151.5us; moved the kernel from
//    issue-bound to HBM-bound — the only structural win available)
//  - exact power-of-two counted loop; ptxas software-pipelines it (R5)
//  - 16384 blocks x 256 threads = 2^22 threads, exactly 8 iters/thread:
//    best tail granularity (R6/R7; 32768 overshot, 512-thr blocks washed)
//  - last-block-finalize: no memset node; final block overwrites the
//    poisoned d_out with a plain store and resets scratch for replay (R11)
// Measured plateau: 147.5-149.3us wall, 7.2-7.36 TB/s = 90-93% of spec HBM,
// all compute pipes idle. Bytes (1.074 GB) are irreducible; sm_103a has no
// 256-bit LDG, so the instruction mix is minimal. At the hardware ceiling.

__device__ float    g_scratch = 0.0f;
__device__ unsigned g_count   = 0u;

static __device__ __forceinline__ float bce_contrib(float p, float t) {
    bool is_one = (t != 0.0f);
    float x = is_one ? p : (1.0f - p);
    float l = __logf(x);              // MUFU.LG2 + FMUL(ln2)
    l = fmaxf(l, -100.0f);            // never binds (p in [1e-6, 1-1e-6])
    float w = is_one ? 10.0f : 1.0f;
    return -w * l;
}

__global__ void __launch_bounds__(256)
nbv_loss_kernel(const float4* __restrict__ pred,
                const float4* __restrict__ targ,
                float* __restrict__ out,
                int n4) {
    const int stride = gridDim.x * blockDim.x;
    const int tid = blockIdx.x * blockDim.x + threadIdx.x;
    const int iters = n4 / stride;    // exact uniform trip count (8)

    float acc = 0.0f;
    int i = tid;
    for (int k = 0; k < iters; ++k, i += stride) {
        float4 pv = pred[i];
        float4 tv = targ[i];
        acc += bce_contrib(pv.x, tv.x);
        acc += bce_contrib(pv.y, tv.y);
        acc += bce_contrib(pv.z, tv.z);
        acc += bce_contrib(pv.w, tv.w);
    }
    // Remainder (empty for n4 = 2^25 with 2^22 threads)
    for (; i < n4; i += stride) {
        float4 pv = pred[i];
        float4 tv = targ[i];
        acc += bce_contrib(pv.x, tv.x);
        acc += bce_contrib(pv.y, tv.y);
        acc += bce_contrib(pv.z, tv.z);
        acc += bce_contrib(pv.w, tv.w);
    }

    // warp reduction
    #pragma unroll
    for (int off = 16; off > 0; off >>= 1)
        acc += __shfl_xor_sync(0xFFFFFFFFu, acc, off);

    __shared__ float warp_sums[8];
    int lane = threadIdx.x & 31;
    int wid  = threadIdx.x >> 5;
    if (lane == 0) warp_sums[wid] = acc;
    __syncthreads();

    if (wid == 0) {
        float v = (lane < 8) ? warp_sums[lane] : 0.0f;
        #pragma unroll
        for (int off = 4; off > 0; off >>= 1)
            v += __shfl_xor_sync(0xFFFFFFFFu, v, off);
        if (lane == 0) {
            atomicAdd(&g_scratch, v);
            __threadfence();
            unsigned old = atomicInc(&g_count, gridDim.x - 1);
            if (old == gridDim.x - 1) {
                // Last block: all prior atomicAdds are visible (fenced +
                // ordered before their atomicInc). Publish and reset.
                float total = *((volatile float*)&g_scratch);
                out[0] = total;          // plain store overwrites poison
                g_scratch = 0.0f;        // ready for next graph replay
                // g_count wrapped to 0 automatically via atomicInc.
            }
        }
    }
}

extern "C" void kernel_launch(void* const* d_in, const int* in_sizes, int n_in,
                              void* d_out, int out_size) {
    const float4* pred = (const float4*)d_in[0];
    const float4* targ = (const float4*)d_in[1];
    float* out = (float*)d_out;

    int n = in_sizes[0];           // 134217728, divisible by 4
    int n4 = n >> 2;               // 33554432 = 2^25 float4 elements

    const int threads = 256;
    const int blocks = 16384;      // 2^22 threads -> exactly 8 iters/thread
    nbv_loss_kernel<<<blocks, threads>>>(pred, targ, out, n4);
}

// round 13
// speedup vs baseline: 1.0187x; 1.0187x over previous
#include <cuda_runtime.h>
#include <cuda_bf16.h>

// NBVLoss: weighted BCE reduction (HBM-bound streaming sum, ~1.07 GB read).
//   out = 10 * sum_{t==1} -max(log(p), -100) + 1 * sum_{t==0} -max(log(1-p), -100)
// target is exactly 0/1 -> one MUFU.LG2 per element; math fully hidden.
//
// FINAL — R7 configuration, the measured optimum of a 12-round sweep:
//  - single __logf per element (R2: 296 -> 151.5us; issue-bound -> HBM-bound)
//  - exact power-of-two counted loop; ptxas software-pipelines it (R5)
//  - 16384 blocks x 256 threads = 2^22 threads, exactly 8 iters/thread
//    (best tail granularity: 4096/8192 coarser & slower, 32768 overshot,
//    512-thr blocks washed)
//  - memset node + one atomicAdd per block: measured FASTER than the
//    last-block-finalize pattern (R11/R12: occ 72->65%, +3us kernel —
//    the fence+counter tail costs more than the free 4-byte memset node)
// Measured: ncu 146.4us, wall 147.5us, 7.36 TB/s = 92.8% of spec HBM,
// all compute pipes idle. Bytes are irreducible. Hardware ceiling reached.

static __device__ __forceinline__ float bce_contrib(float p, float t) {
    bool is_one = (t != 0.0f);
    float x = is_one ? p : (1.0f - p);
    float l = __logf(x);              // MUFU.LG2 + FMUL(ln2)
    l = fmaxf(l, -100.0f);            // never binds (p in [1e-6, 1-1e-6])
    float w = is_one ? 10.0f : 1.0f;
    return -w * l;
}

__global__ void __launch_bounds__(256)
nbv_loss_kernel(const float4* __restrict__ pred,
                const float4* __restrict__ targ,
                float* __restrict__ out,
                int n4) {
    const int stride = gridDim.x * blockDim.x;
    const int tid = blockIdx.x * blockDim.x + threadIdx.x;
    const int iters = n4 / stride;    // exact uniform trip count (8)

    float acc = 0.0f;
    int i = tid;
    for (int k = 0; k < iters; ++k, i += stride) {
        float4 pv = pred[i];
        float4 tv = targ[i];
        acc += bce_contrib(pv.x, tv.x);
        acc += bce_contrib(pv.y, tv.y);
        acc += bce_contrib(pv.z, tv.z);
        acc += bce_contrib(pv.w, tv.w);
    }
    // Remainder (empty for n4 = 2^25 with 2^22 threads)
    for (; i < n4; i += stride) {
        float4 pv = pred[i];
        float4 tv = targ[i];
        acc += bce_contrib(pv.x, tv.x);
        acc += bce_contrib(pv.y, tv.y);
        acc += bce_contrib(pv.z, tv.z);
        acc += bce_contrib(pv.w, tv.w);
    }

    // warp reduction
    #pragma unroll
    for (int off = 16; off > 0; off >>= 1)
        acc += __shfl_xor_sync(0xFFFFFFFFu, acc, off);

    __shared__ float warp_sums[8];
    int lane = threadIdx.x & 31;
    int wid  = threadIdx.x >> 5;
    if (lane == 0) warp_sums[wid] = acc;
    __syncthreads();

    if (wid == 0) {
        float v = (lane < 8) ? warp_sums[lane] : 0.0f;
        #pragma unroll
        for (int off = 4; off > 0; off >>= 1)
            v += __shfl_xor_sync(0xFFFFFFFFu, v, off);
        if (lane == 0)
            atomicAdd(out, v);
    }
}

extern "C" void kernel_launch(void* const* d_in, const int* in_sizes, int n_in,
                              void* d_out, int out_size) {
    const float4* pred = (const float4*)d_in[0];
    const float4* targ = (const float4*)d_in[1];
    float* out = (float*)d_out;

    int n = in_sizes[0];           // 134217728, divisible by 4
    int n4 = n >> 2;               // 33554432 = 2^25 float4 elements

    cudaMemsetAsync(out, 0, sizeof(float));

    const int threads = 256;
    const int blocks = 16384;      // 2^22 threads -> exactly 8 iters/thread
    nbv_loss_kernel<<<blocks, threads>>>(pred, targ, out, n4);
}